// round 8
// baseline (speedup 1.0000x reference)
#include <cuda_runtime.h>
#include <math.h>

#define BB   256

// out layout: value [B,32,32,32] | weight [B,32,32] | wp [B,32,32]
#define WOFF      (8388608ull)
#define WPOFF     (8650752ull)

typedef unsigned long long ull;

// fp32 M/Mp (not strictly needed but kept for clarity of k0 GEMM), hi/lo tf32 splits
__device__ float g_Mh [128 * 128];
__device__ float g_Ml [128 * 128];
__device__ float g_Mph[128 * 128];
__device__ float g_Mpl[128 * 128];
__device__ float g_Wvh [128 * 128];
__device__ float g_Wvl [128 * 128];
__device__ float g_Wvph[128 * 128];
__device__ float g_Wvpl[128 * 128];
__device__ float g_Wf1h[256 * 64];
__device__ float g_Wf1l[256 * 64];
__device__ float g_U[BB * 32 * 64];
__device__ float g_V[BB * 32 * 64];

// ---- packed f32x2 helpers (U step) ----
__device__ __forceinline__ ull pk2(float v) {
    ull r; asm("mov.b64 %0, {%1, %1};" : "=l"(r) : "f"(v)); return r;
}
__device__ __forceinline__ ull ffma2(ull a, ull b, ull c) {
    ull d; asm("fma.rn.f32x2 %0, %1, %2, %3;" : "=l"(d) : "l"(a), "l"(b), "l"(c)); return d;
}
__device__ __forceinline__ float2 upk2(ull v) {
    float2 f; asm("mov.b64 {%0, %1}, %2;" : "=f"(f.x), "=f"(f.y) : "l"(v)); return f;
}

// ---- tf32 helpers ----
__device__ __forceinline__ unsigned tf32_of(float x) {
    unsigned r; asm("cvt.rna.tf32.f32 %0, %1;" : "=r"(r) : "f"(x)); return r;
}
__device__ __forceinline__ void split3(float x, unsigned& h, unsigned& l) {
    h = tf32_of(x);
    l = tf32_of(x - __uint_as_float(h));
}
__device__ __forceinline__ void mma_tf32(float d[4], const unsigned a[4],
                                         unsigned b0, unsigned b1) {
    asm("mma.sync.aligned.m16n8k8.row.col.f32.tf32.tf32.f32 "
        "{%0,%1,%2,%3}, {%4,%5,%6,%7}, {%8,%9}, {%0,%1,%2,%3};"
        : "+f"(d[0]), "+f"(d[1]), "+f"(d[2]), "+f"(d[3])
        : "r"(a[0]), "r"(a[1]), "r"(a[2]), "r"(a[3]), "r"(b0), "r"(b1));
}
__device__ __forceinline__ void mma3(float d[4], const unsigned Ah[4], const unsigned Al[4],
                                     unsigned b0h, unsigned b1h, unsigned b0l, unsigned b1l) {
    mma_tf32(d, Ah, b0h, b1h);
    mma_tf32(d, Ah, b0l, b1l);
    mma_tf32(d, Al, b0h, b1h);
}

__device__ __forceinline__ float warp_max(float v) {
    #pragma unroll
    for (int o = 16; o; o >>= 1) v = fmaxf(v, __shfl_xor_sync(0xffffffffu, v, o));
    return v;
}
__device__ __forceinline__ float warp_sum(float v) {
    #pragma unroll
    for (int o = 16; o; o >>= 1) v += __shfl_xor_sync(0xffffffffu, v, o);
    return v;
}

// ---------------------------------------------------------------------------
// Kernel 0: M = Wq@Wk^T, Mp = Wqp@Wkp^T -> hi/lo splits. grid (16,2,2).
// ---------------------------------------------------------------------------
__global__ void k0_precompute(const float* __restrict__ Wq, const float* __restrict__ Wk,
                              const float* __restrict__ Wqp, const float* __restrict__ Wkp) {
    __shared__ float sA[8 * 128];
    __shared__ float sB[64 * 129];
    const float* A  = blockIdx.z ? Wqp : Wq;
    const float* Bm = blockIdx.z ? Wkp : Wk;
    float* outh     = blockIdx.z ? g_Mph : g_Mh;
    float* outl     = blockIdx.z ? g_Mpl : g_Ml;
    const int e0 = blockIdx.x * 8;
    const int c0 = blockIdx.y * 64;
    const int t  = threadIdx.x;
    for (int idx = t; idx < 1024; idx += 256) sA[idx] = A[e0 * 128 + idx];
    for (int idx = t; idx < 64 * 128; idx += 256) {
        int r = idx >> 7, d = idx & 127;
        sB[r * 129 + d] = Bm[(c0 + r) * 128 + d];
    }
    __syncthreads();
    const int w = t >> 5, l = t & 31;
    float a0 = 0.f, a1 = 0.f;
    #pragma unroll 8
    for (int d = 0; d < 128; ++d) {
        float av = sA[w * 128 + d];
        a0 = fmaf(av, sB[l * 129 + d], a0);
        a1 = fmaf(av, sB[(l + 32) * 129 + d], a1);
    }
    {
        float h0 = __uint_as_float(tf32_of(a0));
        float h1 = __uint_as_float(tf32_of(a1));
        int i0 = (e0 + w) * 128 + c0 + l;
        int i1 = i0 + 32;
        outh[i0] = h0; outl[i0] = __uint_as_float(tf32_of(a0 - h0));
        outh[i1] = h1; outl[i1] = __uint_as_float(tf32_of(a1 - h1));
    }
}

// hi/lo conversion of Wv, Wvp, Wf1. grid 192 x 256.
__global__ void k0_convert(const float* __restrict__ Wv, const float* __restrict__ Wvp,
                           const float* __restrict__ Wf1) {
    int idx = blockIdx.x * 256 + threadIdx.x;       // 0..49151
    const float* src; float* dh; float* dl; int o;
    if (idx < 16384)      { src = Wv;  dh = g_Wvh;  dl = g_Wvl;  o = idx; }
    else if (idx < 32768) { src = Wvp; dh = g_Wvph; dl = g_Wvpl; o = idx - 16384; }
    else                  { src = Wf1; dh = g_Wf1h; dl = g_Wf1l; o = idx - 32768; }
    float v = src[o];
    float h = __uint_as_float(tf32_of(v));
    dh[o] = h;
    dl[o] = __uint_as_float(tf32_of(v - h));
}

// ---------------------------------------------------------------------------
// k1 tensor-core GEMM cores. Warp layout: lq = l>>2 (row group), lr = l&3.
// 128-wide: warp w covers output cols 16w..16w+15 (2 n8 tiles), M=32 (2 m16).
// 64-wide:  warp w covers output cols 8w..8w+7 (1 n8 tile).
// B staged in 16x(128|weights) hi/lo smem chunks.
// ---------------------------------------------------------------------------
__device__ __forceinline__ void loadA(const float* __restrict__ X, int xstr,
                                      int i0, int f1, int lq,
                                      unsigned Ah[4], unsigned Al[4]) {
    split3(X[(i0 + lq    ) * xstr + f1    ], Ah[0], Al[0]);
    split3(X[(i0 + lq + 8) * xstr + f1    ], Ah[1], Al[1]);
    split3(X[(i0 + lq    ) * xstr + f1 + 4], Ah[2], Al[2]);
    split3(X[(i0 + lq + 8) * xstr + f1 + 4], Ah[3], Al[3]);
}

__device__ void tc_gemm128(const float* __restrict__ X, int xstr,
                           const float* __restrict__ gWh, const float* __restrict__ gWl,
                           int nchunks, float D[2][2][4],
                           float* __restrict__ s_Bh, float* __restrict__ s_Bl,
                           int w, int lq, int lr, int t) {
    #pragma unroll 1
    for (int ck = 0; ck < nchunks; ++ck) {
        __syncthreads();
        const float* sh = gWh + ck * 2048;
        const float* sl = gWl + ck * 2048;
        for (int i = t; i < 2048; i += 256) {
            int r = i >> 7, c = i & 127;
            s_Bh[r * 132 + c] = sh[i];
            s_Bl[r * 132 + c] = sl[i];
        }
        __syncthreads();
        #pragma unroll
        for (int kt = 0; kt < 2; ++kt) {
            const int f1 = ck * 16 + kt * 8 + lr;
            const int kl = kt * 8 + lr;
            unsigned Ah[2][4], Al[2][4];
            loadA(X, xstr, 0,  f1, lq, Ah[0], Al[0]);
            loadA(X, xstr, 16, f1, lq, Ah[1], Al[1]);
            #pragma unroll
            for (int nt = 0; nt < 2; ++nt) {
                const int n = 16 * w + nt * 8 + lq;
                unsigned b0h = __float_as_uint(s_Bh[kl * 132 + n]);
                unsigned b1h = __float_as_uint(s_Bh[(kl + 4) * 132 + n]);
                unsigned b0l = __float_as_uint(s_Bl[kl * 132 + n]);
                unsigned b1l = __float_as_uint(s_Bl[(kl + 4) * 132 + n]);
                mma3(D[0][nt], Ah[0], Al[0], b0h, b1h, b0l, b1l);
                mma3(D[1][nt], Ah[1], Al[1], b0h, b1h, b0l, b1l);
            }
        }
    }
}

__device__ void tc_gemm64(const float* __restrict__ X, int xstr,
                          const float* __restrict__ gWh, const float* __restrict__ gWl,
                          float D[2][4],
                          float* __restrict__ s_Bh, float* __restrict__ s_Bl,
                          int w, int lq, int lr, int t) {
    #pragma unroll 1
    for (int ck = 0; ck < 4; ++ck) {            // 32 k-rows per chunk, K=128
        __syncthreads();
        const float* sh = gWh + ck * 2048;
        const float* sl = gWl + ck * 2048;
        for (int i = t; i < 2048; i += 256) {
            int r = i >> 6, c = i & 63;
            s_Bh[r * 66 + c] = sh[i];
            s_Bl[r * 66 + c] = sl[i];
        }
        __syncthreads();
        #pragma unroll
        for (int kt = 0; kt < 4; ++kt) {
            const int f1 = ck * 32 + kt * 8 + lr;
            const int kl = kt * 8 + lr;
            unsigned Ah[2][4], Al[2][4];
            loadA(X, xstr, 0,  f1, lq, Ah[0], Al[0]);
            loadA(X, xstr, 16, f1, lq, Ah[1], Al[1]);
            const int n = 8 * w + lq;
            unsigned b0h = __float_as_uint(s_Bh[kl * 66 + n]);
            unsigned b1h = __float_as_uint(s_Bh[(kl + 4) * 66 + n]);
            unsigned b0l = __float_as_uint(s_Bl[kl * 66 + n]);
            unsigned b1l = __float_as_uint(s_Bl[(kl + 4) * 66 + n]);
            mma3(D[0], Ah[0], Al[0], b0h, b1h, b0l, b1l);
            mma3(D[1], Ah[1], Al[1], b0h, b1h, b0l, b1l);
        }
    }
}

__device__ __forceinline__ void storeD128(float* __restrict__ Y, int ystr,
                                          const float D[2][2][4],
                                          int w, int lq, int lr, bool do_tanh) {
    #pragma unroll
    for (int mt = 0; mt < 2; ++mt)
        #pragma unroll
        for (int nt = 0; nt < 2; ++nt) {
            int i = mt * 16 + lq;
            int n = 16 * w + nt * 8 + 2 * lr;
            float d0 = D[mt][nt][0], d1 = D[mt][nt][1];
            float d2 = D[mt][nt][2], d3 = D[mt][nt][3];
            if (do_tanh) { d0 = tanhf(d0); d1 = tanhf(d1); d2 = tanhf(d2); d3 = tanhf(d3); }
            Y[i * ystr + n]           = d0;
            Y[i * ystr + n + 1]       = d1;
            Y[(i + 8) * ystr + n]     = d2;
            Y[(i + 8) * ystr + n + 1] = d3;
        }
}

// scores SC[i][j] = sum_f A[i][f] * B[j][f]; warp w -> tile (mt=w>>2, nt=w&3)
__device__ void tc_scores(const float* __restrict__ A, int astr,
                          const float* __restrict__ B, int bstr,
                          float* __restrict__ SC, int w, int lq, int lr) {
    const int mt = w >> 2, nt = w & 3;
    float Ds[4] = {0.f, 0.f, 0.f, 0.f};
    #pragma unroll 4
    for (int kt = 0; kt < 16; ++kt) {
        const int f1 = kt * 8 + lr;
        unsigned Ah[4], Al[4];
        loadA(A, astr, mt * 16, f1, lq, Ah, Al);
        unsigned b0h, b0l, b1h, b1l;
        split3(B[(nt * 8 + lq) * bstr + f1    ], b0h, b0l);
        split3(B[(nt * 8 + lq) * bstr + f1 + 4], b1h, b1l);
        mma3(Ds, Ah, Al, b0h, b1h, b0l, b1l);
    }
    const int i = mt * 16 + lq, j = nt * 8 + 2 * lr;
    SC[i * 33 + j]           = Ds[0];
    SC[i * 33 + j + 1]       = Ds[1];
    SC[(i + 8) * 33 + j]     = Ds[2];
    SC[(i + 8) * 33 + j + 1] = Ds[3];
}

// ---------------------------------------------------------------------------
// Kernel 1: one block per batch. smem = 96,000 B -> 2 blocks/SM.
// ---------------------------------------------------------------------------
#define SM1_BYTES 96000
#define SOFTMAX_SCALE 0.08838834764831843f   // 1/sqrt(128)

extern "C" __global__ void __launch_bounds__(256, 2)
k1_batch(const float* __restrict__ states, const float* __restrict__ policies,
         const float* __restrict__ actions, const float* __restrict__ states_people,
         const float* __restrict__ actions_people, float* __restrict__ out) {
    extern __shared__ __align__(16) float sm[];
    float* s_oa  = sm;                 // 32 x 129
    float* s_oap = s_oa  + 4128;       // 32 x 129
    float* s_t   = s_oap + 4128;       // 32 x 130 (t/tp/va/vp/avp)
    float* s_D   = s_t   + 4160;       // 32 x 33  (pol - act)
    float* s_w   = s_D   + 1056;       // 32 x 32
    float* s_wp  = s_w   + 1024;       // 32 x 33
    float* s_A1  = s_wp  + 1056;       // 32 x 66  (early: sc 32x33)
    float* s_C1  = s_A1  + 2112;       // 32 x 66  (early: sp 32x33)
    float* s_Bh  = s_C1  + 2112;       // 2112: staged B hi
    float* s_Bl  = s_Bh  + 2112;       // 2112: staged B lo
    float* s_sc  = s_A1;
    float* s_sp  = s_C1;

    const int b = blockIdx.x;
    const int t = threadIdx.x;
    const int w = t >> 5, l = t & 31;
    const int lq = l >> 2, lr = l & 3;

    // --- load inputs ---
    {
        const float* st  = states         + (size_t)b * 32 * 96;
        const float* ac  = actions        + (size_t)b * 1024;
        const float* stp = states_people  + (size_t)b * 32 * 96;
        const float* acp = actions_people + (size_t)b * 1024;
        const float* po  = policies       + (size_t)b * 1024;
        for (int idx = t; idx < 4096; idx += 256) {
            int i = idx >> 7, c = idx & 127;
            s_oa [i * 129 + c] = (c < 96) ? st [i * 96 + c] : ac [i * 32 + c - 96];
            s_oap[i * 129 + c] = (c < 96) ? stp[i * 96 + c] : acp[i * 32 + c - 96];
        }
        for (int idx = t; idx < 1024; idx += 256)
            s_D[(idx >> 5) * 33 + (idx & 31)] = po[idx] - ac[idx];
    }
    // (tc_gemm's leading __syncthreads covers visibility)

    // --- t = oa @ M -> scores ---
    {
        float Dt[2][2][4] = {};
        tc_gemm128(s_oa, 129, g_Mh, g_Ml, 8, Dt, s_Bh, s_Bl, w, lq, lr, t);
        storeD128(s_t, 130, Dt, w, lq, lr, false);
        __syncthreads();
        tc_scores(s_t, 130, s_oa, 129, s_sc, w, lq, lr);
        __syncthreads();
    }
    // --- tp = oa @ Mp -> scores_p ---
    {
        float Dtp[2][2][4] = {};
        tc_gemm128(s_oa, 129, g_Mph, g_Mpl, 8, Dtp, s_Bh, s_Bl, w, lq, lr, t);
        storeD128(s_t, 130, Dtp, w, lq, lr, false);
        __syncthreads();
        tc_scores(s_t, 130, s_oap, 129, s_sp, w, lq, lr);
        __syncthreads();
    }

    // --- column softmaxes ---
    {
        #pragma unroll
        for (int k = 0; k < 4; ++k) {
            int a = w + 8 * k;
            float v  = s_sc[l * 33 + a] * SOFTMAX_SCALE;
            float m  = warp_max(v);
            float e  = expf(v - m);
            float s  = warp_sum(e);
            float wg = e / s;
            s_w[a * 32 + l] = wg;
            out[WOFF + ((size_t)b * 32 + a) * 32 + l] = wg;
            float v2 = s_sp[l * 33 + a] * SOFTMAX_SCALE;
            float m2 = warp_max(v2);
            float e2 = expf(v2 - m2);
            float s2 = warp_sum(e2);
            s_wp[l * 33 + a] = e2 / s2;
        }
    }
    __syncthreads();   // frees sc/sp regions for A1/C1

    // === va -> A1 ; vp -> V(gmem) ; avp -> C1 ===
    float DA1[2][4] = {};
    {
        // va = tanh(oa @ Wv); keep pre-activation frags for vp
        float Dva[2][2][4] = {};
        tc_gemm128(s_oa, 129, g_Wvh, g_Wvl, 8, Dva, s_Bh, s_Bl, w, lq, lr, t);
        storeD128(s_t, 130, Dva, w, lq, lr, true);        // va
        // A1 = va @ Wf1_top (leading sync inside orders va stores)
        tc_gemm64(s_t, 130, g_Wf1h, g_Wf1l, DA1, s_Bh, s_Bl, w, lq, lr, t);
        {
            int n = 8 * w + 2 * lr;
            #pragma unroll
            for (int mt = 0; mt < 2; ++mt) {
                int i = mt * 16 + lq;
                s_A1[i * 66 + n]           = DA1[mt][0];
                s_A1[i * 66 + n + 1]       = DA1[mt][1];
                s_A1[(i + 8) * 66 + n]     = DA1[mt][2];
                s_A1[(i + 8) * 66 + n + 1] = DA1[mt][3];
            }
        }
        // vp_pre = va_pre + (pol-act) @ Wv[96:,:]  (accumulate into Dva)
        tc_gemm128(s_D, 33, g_Wvh + 96 * 128, g_Wvl + 96 * 128, 2, Dva,
                   s_Bh, s_Bl, w, lq, lr, t);
        storeD128(s_t, 130, Dva, w, lq, lr, true);        // vp
        // B1 = vp @ Wf1_top; V = (B1 - A1)/32 -> gmem
        float DB1[2][4] = {};
        tc_gemm64(s_t, 130, g_Wf1h, g_Wf1l, DB1, s_Bh, s_Bl, w, lq, lr, t);
        {
            float* gV = g_V + (size_t)b * 2048;
            int n = 8 * w + 2 * lr;
            #pragma unroll
            for (int mt = 0; mt < 2; ++mt) {
                int i = mt * 16 + lq;
                gV[i * 64 + n]           = (DB1[mt][0] - DA1[mt][0]) * 0.03125f;
                gV[i * 64 + n + 1]       = (DB1[mt][1] - DA1[mt][1]) * 0.03125f;
                gV[(i + 8) * 64 + n]     = (DB1[mt][2] - DA1[mt][2]) * 0.03125f;
                gV[(i + 8) * 64 + n + 1] = (DB1[mt][3] - DA1[mt][3]) * 0.03125f;
            }
        }
        // avp = tanh(oap @ Wvp); C1 = avp @ Wf1_bot
        float Dap[2][2][4] = {};
        tc_gemm128(s_oap, 129, g_Wvph, g_Wvpl, 8, Dap, s_Bh, s_Bl, w, lq, lr, t);
        storeD128(s_t, 130, Dap, w, lq, lr, true);
        float DC1[2][4] = {};
        tc_gemm64(s_t, 130, g_Wf1h + 8192, g_Wf1l + 8192, DC1, s_Bh, s_Bl, w, lq, lr, t);
        {
            int n = 8 * w + 2 * lr;
            #pragma unroll
            for (int mt = 0; mt < 2; ++mt) {
                int i = mt * 16 + lq;
                s_C1[i * 66 + n]           = DC1[mt][0];
                s_C1[i * 66 + n + 1]       = DC1[mt][1];
                s_C1[(i + 8) * 66 + n]     = DC1[mt][2];
                s_C1[(i + 8) * 66 + n + 1] = DC1[mt][3];
            }
        }
    }
    __syncthreads();   // A1/C1/w/wp complete, cross-warp reads next

    // --- wp to global ---
    for (int idx = t; idx < 1024; idx += 256)
        out[WPOFF + (size_t)b * 1024 + idx] = s_wp[(idx >> 5) * 33 + (idx & 31)];

    // --- U[a, 2l..2l+1] = (w[a,:]@A1 + wp[a,:]@C1)/32, warp rows 4w..4w+3 ---
    {
        const int r0 = 4 * w;
        ull uacc[4] = {0, 0, 0, 0};
        #pragma unroll 4
        for (int j = 0; j < 32; ++j) {
            ull wv = *reinterpret_cast<const ull*>(&s_A1[j * 66 + 2 * l]);
            #pragma unroll
            for (int r = 0; r < 4; ++r)
                uacc[r] = ffma2(pk2(s_w[(r0 + r) * 32 + j]), wv, uacc[r]);
        }
        #pragma unroll 4
        for (int p = 0; p < 32; ++p) {
            ull wv = *reinterpret_cast<const ull*>(&s_C1[p * 66 + 2 * l]);
            #pragma unroll
            for (int r = 0; r < 4; ++r)
                uacc[r] = ffma2(pk2(s_wp[(r0 + r) * 33 + p]), wv, uacc[r]);
        }
        float* gU = g_U + (size_t)b * 2048;
        #pragma unroll
        for (int r = 0; r < 4; ++r) {
            float2 p = upk2(uacc[r]);
            *reinterpret_cast<float2*>(&gU[(r0 + r) * 64 + 2 * l]) =
                make_float2(p.x * 0.03125f, p.y * 0.03125f);
        }
    }
}

// ---------------------------------------------------------------------------
// Kernel 2 (round-7 proven): tensor-core 3xTF32 value GEMM.
// ---------------------------------------------------------------------------
extern "C" __global__ void __launch_bounds__(256)
k2_value(const float* __restrict__ Wf2, float* __restrict__ out) {
    __shared__ float    sV [32 * 68];
    __shared__ float    sU [8 * 64];
    __shared__ float    swt[8 * 32];
    __shared__ unsigned sW2h[64 * 36];
    __shared__ unsigned sW2l[64 * 36];

    const int t  = threadIdx.x;
    const int b  = blockIdx.x >> 2;
    const int a0 = (blockIdx.x & 3) * 8;

    for (int idx = t; idx < 2048; idx += 256) {
        int i = idx >> 6, f = idx & 63;
        sV[i * 68 + f] = g_V[(size_t)b * 2048 + idx];
    }
    for (int idx = t; idx < 512; idx += 256)
        sU[idx] = g_U[(size_t)b * 2048 + a0 * 64 + idx];
    {
        int a = t >> 5, i = t & 31;
        swt[a * 32 + i] = out[WOFF + ((size_t)b * 32 + a0 + a) * 32 + i];
    }
    for (int idx = t; idx < 2048; idx += 256) {
        int f = idx >> 5, n = idx & 31;
        float v = Wf2[idx];
        unsigned hb = tf32_of(v);
        sW2h[f * 36 + n] = hb;
        sW2l[f * 36 + n] = tf32_of(v - __uint_as_float(hb));
    }
    __syncthreads();

    const int w = t >> 5, l = t & 31;
    const int lq = l >> 2;
    const int lr = l & 3;
    const float* Urow = &sU [w * 64];
    const float* wrow = &swt[w * 32];

    float Uf[8][2];
    #pragma unroll
    for (int kt = 0; kt < 8; ++kt) {
        Uf[kt][0] = Urow[kt * 8 + lr];
        Uf[kt][1] = Urow[kt * 8 + lr + 4];
    }
    float wm[2][2];
    #pragma unroll
    for (int mt = 0; mt < 2; ++mt) {
        wm[mt][0] = wrow[mt * 16 + lq];
        wm[mt][1] = wrow[mt * 16 + lq + 8];
    }

    float D[2][4][4];
    #pragma unroll
    for (int mt = 0; mt < 2; ++mt)
        #pragma unroll
        for (int nt = 0; nt < 4; ++nt)
            #pragma unroll
            for (int q = 0; q < 4; ++q) D[mt][nt][q] = 0.f;

    #pragma unroll
    for (int kt = 0; kt < 8; ++kt) {
        const int f1 = kt * 8 + lr;
        unsigned Ah[2][4], Al[2][4];
        #pragma unroll
        for (int mt = 0; mt < 2; ++mt) {
            const int i1 = mt * 16 + lq;
            float v00 = sV[i1 * 68 + f1];
            float v10 = sV[(i1 + 8) * 68 + f1];
            float v01 = sV[i1 * 68 + f1 + 4];
            float v11 = sV[(i1 + 8) * 68 + f1 + 4];
            float h0 = fmaf(wm[mt][0], v00, Uf[kt][0]);
            float h1 = fmaf(wm[mt][1], v10, Uf[kt][0]);
            float h2 = fmaf(wm[mt][0], v01, Uf[kt][1]);
            float h3 = fmaf(wm[mt][1], v11, Uf[kt][1]);
            h0 = fmaxf(h0, 0.f) + 0.01f * fminf(h0, 0.f);
            h1 = fmaxf(h1, 0.f) + 0.01f * fminf(h1, 0.f);
            h2 = fmaxf(h2, 0.f) + 0.01f * fminf(h2, 0.f);
            h3 = fmaxf(h3, 0.f) + 0.01f * fminf(h3, 0.f);
            Ah[mt][0] = tf32_of(h0);
            Ah[mt][1] = tf32_of(h1);
            Ah[mt][2] = tf32_of(h2);
            Ah[mt][3] = tf32_of(h3);
            Al[mt][0] = tf32_of(h0 - __uint_as_float(Ah[mt][0]));
            Al[mt][1] = tf32_of(h1 - __uint_as_float(Ah[mt][1]));
            Al[mt][2] = tf32_of(h2 - __uint_as_float(Ah[mt][2]));
            Al[mt][3] = tf32_of(h3 - __uint_as_float(Ah[mt][3]));
        }
        #pragma unroll
        for (int nt = 0; nt < 4; ++nt) {
            const int bo = f1 * 36 + nt * 8 + lq;
            unsigned b0h = sW2h[bo], b1h = sW2h[bo + 4 * 36];
            unsigned b0l = sW2l[bo], b1l = sW2l[bo + 4 * 36];
            #pragma unroll
            for (int mt = 0; mt < 2; ++mt) {
                mma_tf32(D[mt][nt], Ah[mt], b0h, b1h);
                mma_tf32(D[mt][nt], Ah[mt], b0l, b1l);
                mma_tf32(D[mt][nt], Al[mt], b0h, b1h);
            }
        }
    }

    const size_t base = (((size_t)b * 32) + a0 + w) * 1024;
    #pragma unroll
    for (int mt = 0; mt < 2; ++mt) {
        #pragma unroll
        for (int nt = 0; nt < 4; ++nt) {
            const int i1 = mt * 16 + lq;
            const int n  = nt * 8 + 2 * lr;
            *reinterpret_cast<float2*>(&out[base + i1 * 32 + n]) =
                make_float2(D[mt][nt][0], D[mt][nt][1]);
            *reinterpret_cast<float2*>(&out[base + (i1 + 8) * 32 + n]) =
                make_float2(D[mt][nt][2], D[mt][nt][3]);
        }
    }
}

// ---------------------------------------------------------------------------
extern "C" void kernel_launch(void* const* d_in, const int* in_sizes, int n_in,
                              void* d_out, int out_size) {
    const float* states         = (const float*)d_in[0];
    const float* policies       = (const float*)d_in[1];
    const float* actions        = (const float*)d_in[2];
    const float* states_people  = (const float*)d_in[3];
    const float* actions_people = (const float*)d_in[4];
    const float* Wk  = (const float*)d_in[5];
    const float* Wq  = (const float*)d_in[6];
    const float* Wv  = (const float*)d_in[7];
    const float* Wkp = (const float*)d_in[8];
    const float* Wqp = (const float*)d_in[9];
    const float* Wvp = (const float*)d_in[10];
    const float* Wf1 = (const float*)d_in[11];
    const float* Wf2 = (const float*)d_in[12];
    float* out = (float*)d_out;

    k0_convert<<<192, 256>>>(Wv, Wvp, Wf1);
    k0_precompute<<<dim3(16, 2, 2), 256>>>(Wq, Wk, Wqp, Wkp);

    cudaFuncSetAttribute(k1_batch, cudaFuncAttributeMaxDynamicSharedMemorySize, SM1_BYTES);
    k1_batch<<<256, 256, SM1_BYTES>>>(states, policies, actions,
                                      states_people, actions_people, out);

    k2_value<<<1024, 256>>>(Wf2, out);
}

// round 9
// speedup vs baseline: 1.0298x; 1.0298x over previous
#include <cuda_runtime.h>
#include <math.h>

#define BB   256

// out layout: value [B,32,32,32] | weight [B,32,32] | wp [B,32,32]
#define WOFF      (8388608ull)
#define WPOFF     (8650752ull)

typedef unsigned long long ull;

__device__ float g_M [128 * 128];
__device__ float g_Mp[128 * 128];
__device__ float g_U [BB * 32 * 64];
__device__ float g_V [BB * 32 * 64];
__device__ unsigned g_W2h[64 * 32];
__device__ unsigned g_W2l[64 * 32];

// ---- packed f32x2 helpers ----
__device__ __forceinline__ ull pk2(float v) {
    ull r; asm("mov.b64 %0, {%1, %1};" : "=l"(r) : "f"(v)); return r;
}
__device__ __forceinline__ ull ffma2(ull a, ull b, ull c) {
    ull d; asm("fma.rn.f32x2 %0, %1, %2, %3;" : "=l"(d) : "l"(a), "l"(b), "l"(c)); return d;
}
__device__ __forceinline__ float2 upk2(ull v) {
    float2 f; asm("mov.b64 {%0, %1}, %2;" : "=f"(f.x), "=f"(f.y) : "l"(v)); return f;
}

// ---- tf32 helpers (k2) ----
__device__ __forceinline__ unsigned tf32_of(float x) {
    unsigned r; asm("cvt.rna.tf32.f32 %0, %1;" : "=r"(r) : "f"(x)); return r;
}
__device__ __forceinline__ void mma_tf32(float d[4], const unsigned a[4],
                                         unsigned b0, unsigned b1) {
    asm("mma.sync.aligned.m16n8k8.row.col.f32.tf32.tf32.f32 "
        "{%0,%1,%2,%3}, {%4,%5,%6,%7}, {%8,%9}, {%0,%1,%2,%3};"
        : "+f"(d[0]), "+f"(d[1]), "+f"(d[2]), "+f"(d[3])
        : "r"(a[0]), "r"(a[1]), "r"(a[2]), "r"(a[3]), "r"(b0), "r"(b1));
}

__device__ __forceinline__ float warp_max(float v) {
    #pragma unroll
    for (int o = 16; o; o >>= 1) v = fmaxf(v, __shfl_xor_sync(0xffffffffu, v, o));
    return v;
}
__device__ __forceinline__ float warp_sum(float v) {
    #pragma unroll
    for (int o = 16; o; o >>= 1) v += __shfl_xor_sync(0xffffffffu, v, o);
    return v;
}

// ---------------------------------------------------------------------------
// Kernel 0 (merged): blocks 0..255: M/Mp GEMMs (8x16 tiles, split-K 2).
//                    blocks 256..263: W2 hi/lo tf32 split.
// ---------------------------------------------------------------------------
__global__ void k0_all(const float* __restrict__ Wq, const float* __restrict__ Wk,
                       const float* __restrict__ Wqp, const float* __restrict__ Wkp,
                       const float* __restrict__ Wf2) {
    const int bx = blockIdx.x;
    const int t  = threadIdx.x;
    if (bx >= 256) {
        int idx = (bx - 256) * 256 + t;          // 0..2047
        float v = Wf2[idx];
        unsigned h = tf32_of(v);
        g_W2h[idx] = h;
        g_W2l[idx] = tf32_of(v - __uint_as_float(h));
        return;
    }
    __shared__ float sA[8 * 128];
    __shared__ float sB[16 * 129];
    __shared__ float sR[128 * 2];
    const int mat = bx >> 7;
    const int e0  = ((bx >> 3) & 15) * 8;
    const int c0  = (bx & 7) * 16;
    const float* A  = mat ? Wqp : Wq;
    const float* Bm = mat ? Wkp : Wk;
    float* out      = mat ? g_Mp : g_M;
    for (int i = t; i < 1024; i += 256) sA[i] = A[e0 * 128 + i];
    for (int i = t; i < 2048; i += 256) {
        int r = i >> 7, d = i & 127;
        sB[r * 129 + d] = Bm[(c0 + r) * 128 + d];
    }
    __syncthreads();
    const int kh = t >> 7, r = (t >> 4) & 7, c = t & 15;
    float acc = 0.f;
    const int d0 = kh * 64;
    #pragma unroll 8
    for (int d = 0; d < 64; ++d)
        acc = fmaf(sA[r * 128 + d0 + d], sB[c * 129 + d0 + d], acc);
    sR[(r * 16 + c) * 2 + kh] = acc;
    __syncthreads();
    if (t < 128) {
        int rr = t >> 4, cc = t & 15;
        out[(e0 + rr) * 128 + c0 + cc] = sR[t * 2] + sR[t * 2 + 1];
    }
}

// ---------------------------------------------------------------------------
// k1 GEMM cores. Warp w owns rows r0=4w..4w+3. Weights staged in s_Wst.
// ---------------------------------------------------------------------------
__device__ __forceinline__ void mm_chunk128(const float* __restrict__ X, int xstr, int e0,
                                            const float* __restrict__ Ws,
                                            ull acc[4][2], int r0, int l) {
    #pragma unroll 4
    for (int e = 0; e < 32; ++e) {
        ulonglong2 wv = *reinterpret_cast<const ulonglong2*>(&Ws[e * 128 + 4 * l]);
        #pragma unroll
        for (int r = 0; r < 4; ++r) {
            ull xx = pk2(X[(r0 + r) * xstr + e0 + e]);
            acc[r][0] = ffma2(xx, wv.x, acc[r][0]);
            acc[r][1] = ffma2(xx, wv.y, acc[r][1]);
        }
    }
}

// 64 e-rows x 64 cols chunk with DUPLICATED X (ull per element, stride 130)
__device__ __forceinline__ void mm_chunk64d(const ull* __restrict__ Xd, int e0,
                                            const float* __restrict__ Ws,
                                            ull acc[4], int r0, int l) {
    #pragma unroll 4
    for (int e = 0; e < 64; ++e) {
        ull wv = *reinterpret_cast<const ull*>(&Ws[e * 64 + 2 * l]);
        #pragma unroll
        for (int r = 0; r < 4; ++r)
            acc[r] = ffma2(Xd[(r0 + r) * 130 + e0 + e], wv, acc[r]);
    }
}

// store 128-wide accumulators into the duplicated t-buffer
__device__ __forceinline__ void store128_dup(ull* __restrict__ Yd, ull acc[4][2],
                                             int r0, int l, bool do_tanh) {
    #pragma unroll
    for (int r = 0; r < 4; ++r) {
        float2 p0 = upk2(acc[r][0]);
        float2 p1 = upk2(acc[r][1]);
        float v0 = p0.x, v1 = p0.y, v2 = p1.x, v3 = p1.y;
        if (do_tanh) { v0 = tanhf(v0); v1 = tanhf(v1); v2 = tanhf(v2); v3 = tanhf(v3); }
        ull* row = &Yd[(r0 + r) * 130 + 4 * l];
        row[0] = pk2(v0); row[1] = pk2(v1); row[2] = pk2(v2); row[3] = pk2(v3);
    }
}

// ---------------------------------------------------------------------------
// Kernel 1: one block per batch. smem = 107,392 B -> 2 blocks/SM.
// ---------------------------------------------------------------------------
#define SM1_BYTES 107392
#define SOFTMAX_SCALE 0.08838834764831843f   // 1/sqrt(128)

#define STAGE(SRC) do {                                                    \
    __syncthreads();                                                       \
    { const float4* s4 = reinterpret_cast<const float4*>(SRC);            \
      float4* d4 = reinterpret_cast<float4*>(s_Wst);                      \
      for (int i = t; i < 1024; i += 256) d4[i] = s4[i]; }                \
    __syncthreads();                                                       \
} while (0)

extern "C" __global__ void __launch_bounds__(256, 2)
k1_batch(const float* __restrict__ states, const float* __restrict__ policies,
         const float* __restrict__ actions, const float* __restrict__ states_people,
         const float* __restrict__ actions_people,
         const float* __restrict__ Wv, const float* __restrict__ Wvp,
         const float* __restrict__ Wf1, float* __restrict__ out) {
    extern __shared__ __align__(16) float sm[];
    float* s_oa  = sm;                                   // 32 x 129
    float* s_oap = s_oa  + 4128;                         // 32 x 129
    ull*   s_td  = reinterpret_cast<ull*>(sm + 8256);    // 32 x 130 ull (dup t/tp/va/vp/avp)
    float* s_w   = sm + 8256 + 8320;                     // 32 x 32
    float* s_wp  = s_w   + 1024;                         // 32 x 33
    float* s_A1  = s_wp  + 1056;                         // 32 x 64 (early: sc 32x33)
    float* s_C1  = s_A1  + 2048;                         // 32 x 64 (early: sp 32x33)
    float* s_Wst = s_C1  + 2048;                         // 4096 floats staged weights
    float* s_sc  = s_A1;
    float* s_sp  = s_C1;
    const float* tf = reinterpret_cast<const float*>(s_td);   // dup view: [i*130+f]*2

    const int b = blockIdx.x;
    const int t = threadIdx.x;
    const int w = t >> 5, l = t & 31, r0 = 4 * w;

    const float* ac = actions  + (size_t)b * 1024;
    const float* po = policies + (size_t)b * 1024;

    // --- delta rows (pol - act) in registers, warp-local rows r0..r0+3 ---
    float d_r[4];
    #pragma unroll
    for (int r = 0; r < 4; ++r)
        d_r[r] = po[(r0 + r) * 32 + l] - ac[(r0 + r) * 32 + l];

    // --- load inputs ---
    {
        const float* st  = states         + (size_t)b * 32 * 96;
        const float* stp = states_people  + (size_t)b * 32 * 96;
        const float* acp = actions_people + (size_t)b * 1024;
        for (int idx = t; idx < 4096; idx += 256) {
            int i = idx >> 7, c = idx & 127;
            s_oa [i * 129 + c] = (c < 96) ? st [i * 96 + c] : ac [i * 32 + c - 96];
            s_oap[i * 129 + c] = (c < 96) ? stp[i * 96 + c] : acp[i * 32 + c - 96];
        }
    }

    // --- t = oa @ M (staged); scores -> sc ---
    {
        ull a1[4][2] = {{0,0},{0,0},{0,0},{0,0}};
        #pragma unroll 1
        for (int ck = 0; ck < 4; ++ck) {
            STAGE(g_M + ck * 4096);
            mm_chunk128(s_oa, 129, ck * 32, s_Wst, a1, r0, l);
        }
        store128_dup(s_td, a1, r0, l, false);
        float a0 = 0, s1 = 0, s2 = 0, s3 = 0;
        #pragma unroll 4
        for (int f = 0; f < 128; ++f) {
            float oj = s_oa[l * 129 + f];
            a0 = fmaf(tf[((r0 + 0) * 130 + f) * 2], oj, a0);
            s1 = fmaf(tf[((r0 + 1) * 130 + f) * 2], oj, s1);
            s2 = fmaf(tf[((r0 + 2) * 130 + f) * 2], oj, s2);
            s3 = fmaf(tf[((r0 + 3) * 130 + f) * 2], oj, s3);
        }
        s_sc[(r0 + 0) * 33 + l] = a0;  s_sc[(r0 + 1) * 33 + l] = s1;
        s_sc[(r0 + 2) * 33 + l] = s2;  s_sc[(r0 + 3) * 33 + l] = s3;
    }

    // --- tp = oa @ Mp (staged); scores_p -> sp ---
    {
        ull a2[4][2] = {{0,0},{0,0},{0,0},{0,0}};
        #pragma unroll 1
        for (int ck = 0; ck < 4; ++ck) {
            STAGE(g_Mp + ck * 4096);
            mm_chunk128(s_oa, 129, ck * 32, s_Wst, a2, r0, l);
        }
        store128_dup(s_td, a2, r0, l, false);
        float c0 = 0, c1 = 0, c2 = 0, c3 = 0;
        #pragma unroll 4
        for (int f = 0; f < 128; ++f) {
            float pj = s_oap[l * 129 + f];
            c0 = fmaf(tf[((r0 + 0) * 130 + f) * 2], pj, c0);
            c1 = fmaf(tf[((r0 + 1) * 130 + f) * 2], pj, c1);
            c2 = fmaf(tf[((r0 + 2) * 130 + f) * 2], pj, c2);
            c3 = fmaf(tf[((r0 + 3) * 130 + f) * 2], pj, c3);
        }
        s_sp[(r0 + 0) * 33 + l] = c0;  s_sp[(r0 + 1) * 33 + l] = c1;
        s_sp[(r0 + 2) * 33 + l] = c2;  s_sp[(r0 + 3) * 33 + l] = c3;
    }
    __syncthreads();   // sc/sp complete

    // --- column softmaxes ---
    {
        #pragma unroll
        for (int k = 0; k < 4; ++k) {
            int a = w + 8 * k;
            float v  = s_sc[l * 33 + a] * SOFTMAX_SCALE;
            float m  = warp_max(v);
            float e  = expf(v - m);
            float s  = warp_sum(e);
            float wg = e / s;
            s_w[a * 32 + l] = wg;
            out[WOFF + ((size_t)b * 32 + a) * 32 + l] = wg;
            float v2 = s_sp[l * 33 + a] * SOFTMAX_SCALE;
            float m2 = warp_max(v2);
            float e2 = expf(v2 - m2);
            float s2 = warp_sum(e2);
            s_wp[l * 33 + a] = e2 / s2;
        }
    }
    __syncthreads();   // frees sc/sp regions for A1/C1

    // === va -> A1 ; vp -> V(gmem) ; avp -> C1 ===
    ull a1regs[4];
    {
        // va = tanh(oa @ Wv)
        ull av[4][2] = {{0,0},{0,0},{0,0},{0,0}};
        #pragma unroll 1
        for (int ck = 0; ck < 4; ++ck) {
            STAGE(Wv + ck * 4096);
            mm_chunk128(s_oa, 129, ck * 32, s_Wst, av, r0, l);
        }
        ull va_pre[4][2];
        #pragma unroll
        for (int r = 0; r < 4; ++r) { va_pre[r][0] = av[r][0]; va_pre[r][1] = av[r][1]; }
        store128_dup(s_td, av, r0, l, true);          // va (dup)

        // A1 = va @ Wf1_top
        {
            ull acc[4] = {0, 0, 0, 0};
            #pragma unroll 1
            for (int ck = 0; ck < 2; ++ck) {
                STAGE(Wf1 + ck * 4096);
                mm_chunk64d(s_td, ck * 64, s_Wst, acc, r0, l);
            }
            #pragma unroll
            for (int r = 0; r < 4; ++r) {
                a1regs[r] = acc[r];
                *reinterpret_cast<float2*>(&s_A1[(r0 + r) * 64 + 2 * l]) = upk2(acc[r]);
            }
        }

        // vp = tanh(va_pre + (pol-act) @ Wv[96:,:])
        {
            STAGE(Wv + 96 * 128);
            #pragma unroll 4
            for (int e = 0; e < 32; ++e) {
                ulonglong2 wv = *reinterpret_cast<const ulonglong2*>(&s_Wst[e * 128 + 4 * l]);
                #pragma unroll
                for (int r = 0; r < 4; ++r) {
                    ull xx = pk2(__shfl_sync(0xffffffffu, d_r[r], e));
                    va_pre[r][0] = ffma2(xx, wv.x, va_pre[r][0]);
                    va_pre[r][1] = ffma2(xx, wv.y, va_pre[r][1]);
                }
            }
            store128_dup(s_td, va_pre, r0, l, true);  // vp (dup)
        }

        // V = (vp @ Wf1_top - A1) / 32 -> gmem
        {
            ull acc[4] = {0, 0, 0, 0};
            #pragma unroll 1
            for (int ck = 0; ck < 2; ++ck) {
                STAGE(Wf1 + ck * 4096);
                mm_chunk64d(s_td, ck * 64, s_Wst, acc, r0, l);
            }
            float* gV = g_V + (size_t)b * 2048;
            #pragma unroll
            for (int r = 0; r < 4; ++r) {
                float2 p = upk2(acc[r]);
                float2 a = upk2(a1regs[r]);
                *reinterpret_cast<float2*>(&gV[(r0 + r) * 64 + 2 * l]) =
                    make_float2((p.x - a.x) * 0.03125f, (p.y - a.y) * 0.03125f);
            }
        }

        // avp = tanh(oap @ Wvp) ; C1 = avp @ Wf1_bot
        {
            ull ap[4][2] = {{0,0},{0,0},{0,0},{0,0}};
            #pragma unroll 1
            for (int ck = 0; ck < 4; ++ck) {
                STAGE(Wvp + ck * 4096);
                mm_chunk128(s_oap, 129, ck * 32, s_Wst, ap, r0, l);
            }
            store128_dup(s_td, ap, r0, l, true);
            ull acc[4] = {0, 0, 0, 0};
            #pragma unroll 1
            for (int ck = 0; ck < 2; ++ck) {
                STAGE(Wf1 + 8192 + ck * 4096);
                mm_chunk64d(s_td, ck * 64, s_Wst, acc, r0, l);
            }
            #pragma unroll
            for (int r = 0; r < 4; ++r)
                *reinterpret_cast<float2*>(&s_C1[(r0 + r) * 64 + 2 * l]) = upk2(acc[r]);
        }
    }
    __syncthreads();   // A1/C1 complete (cross-warp reads next)

    // --- wp to global ---
    for (int idx = t; idx < 1024; idx += 256)
        out[WPOFF + (size_t)b * 1024 + idx] = s_wp[(idx >> 5) * 33 + (idx & 31)];

    // --- U[a, 2l..2l+1] = (w[a,:]@A1 + wp[a,:]@C1)/32, warp rows r0..r0+3 ---
    {
        const ull* A1u = reinterpret_cast<const ull*>(s_A1);
        const ull* C1u = reinterpret_cast<const ull*>(s_C1);
        ull uacc[4] = {0, 0, 0, 0};
        #pragma unroll 4
        for (int j = 0; j < 32; ++j) {
            ull wv = A1u[j * 32 + l];
            #pragma unroll
            for (int r = 0; r < 4; ++r)
                uacc[r] = ffma2(pk2(s_w[(r0 + r) * 32 + j]), wv, uacc[r]);
        }
        #pragma unroll 4
        for (int p = 0; p < 32; ++p) {
            ull wv = C1u[p * 32 + l];
            #pragma unroll
            for (int r = 0; r < 4; ++r)
                uacc[r] = ffma2(pk2(s_wp[(r0 + r) * 33 + p]), wv, uacc[r]);
        }
        float* gU = g_U + (size_t)b * 2048;
        #pragma unroll
        for (int r = 0; r < 4; ++r) {
            float2 p = upk2(uacc[r]);
            *reinterpret_cast<float2*>(&gU[(r0 + r) * 64 + 2 * l]) =
                make_float2(p.x * 0.03125f, p.y * 0.03125f);
        }
    }
}

// ---------------------------------------------------------------------------
// Kernel 2 (round-7 proven, W2 pre-split): tensor-core 3xTF32 value GEMM.
// ---------------------------------------------------------------------------
extern "C" __global__ void __launch_bounds__(256)
k2_value(float* __restrict__ out) {
    __shared__ float    sV [32 * 68];
    __shared__ float    sU [8 * 64];
    __shared__ float    swt[8 * 32];
    __shared__ unsigned sW2h[64 * 36];
    __shared__ unsigned sW2l[64 * 36];

    const int t  = threadIdx.x;
    const int b  = blockIdx.x >> 2;
    const int a0 = (blockIdx.x & 3) * 8;

    for (int idx = t; idx < 2048; idx += 256) {
        int i = idx >> 6, f = idx & 63;
        sV[i * 68 + f] = g_V[(size_t)b * 2048 + idx];
    }
    for (int idx = t; idx < 512; idx += 256)
        sU[idx] = g_U[(size_t)b * 2048 + a0 * 64 + idx];
    {
        int a = t >> 5, i = t & 31;
        swt[a * 32 + i] = out[WOFF + ((size_t)b * 32 + a0 + a) * 32 + i];
    }
    for (int idx = t; idx < 2048; idx += 256) {
        int f = idx >> 5, n = idx & 31;
        sW2h[f * 36 + n] = g_W2h[idx];
        sW2l[f * 36 + n] = g_W2l[idx];
    }
    __syncthreads();

    const int w = t >> 5, l = t & 31;
    const int lq = l >> 2;
    const int lr = l & 3;
    const float* Urow = &sU [w * 64];
    const float* wrow = &swt[w * 32];

    float Uf[8][2];
    #pragma unroll
    for (int kt = 0; kt < 8; ++kt) {
        Uf[kt][0] = Urow[kt * 8 + lr];
        Uf[kt][1] = Urow[kt * 8 + lr + 4];
    }
    float wm[2][2];
    #pragma unroll
    for (int mt = 0; mt < 2; ++mt) {
        wm[mt][0] = wrow[mt * 16 + lq];
        wm[mt][1] = wrow[mt * 16 + lq + 8];
    }

    float D[2][4][4];
    #pragma unroll
    for (int mt = 0; mt < 2; ++mt)
        #pragma unroll
        for (int nt = 0; nt < 4; ++nt)
            #pragma unroll
            for (int q = 0; q < 4; ++q) D[mt][nt][q] = 0.f;

    #pragma unroll
    for (int kt = 0; kt < 8; ++kt) {
        const int f1 = kt * 8 + lr;
        unsigned Ah[2][4], Al[2][4];
        #pragma unroll
        for (int mt = 0; mt < 2; ++mt) {
            const int i1 = mt * 16 + lq;
            float v00 = sV[i1 * 68 + f1];
            float v10 = sV[(i1 + 8) * 68 + f1];
            float v01 = sV[i1 * 68 + f1 + 4];
            float v11 = sV[(i1 + 8) * 68 + f1 + 4];
            float h0 = fmaf(wm[mt][0], v00, Uf[kt][0]);
            float h1 = fmaf(wm[mt][1], v10, Uf[kt][0]);
            float h2 = fmaf(wm[mt][0], v01, Uf[kt][1]);
            float h3 = fmaf(wm[mt][1], v11, Uf[kt][1]);
            h0 = fmaxf(h0, 0.f) + 0.01f * fminf(h0, 0.f);
            h1 = fmaxf(h1, 0.f) + 0.01f * fminf(h1, 0.f);
            h2 = fmaxf(h2, 0.f) + 0.01f * fminf(h2, 0.f);
            h3 = fmaxf(h3, 0.f) + 0.01f * fminf(h3, 0.f);
            Ah[mt][0] = tf32_of(h0);
            Ah[mt][1] = tf32_of(h1);
            Ah[mt][2] = tf32_of(h2);
            Ah[mt][3] = tf32_of(h3);
            Al[mt][0] = tf32_of(h0 - __uint_as_float(Ah[mt][0]));
            Al[mt][1] = tf32_of(h1 - __uint_as_float(Ah[mt][1]));
            Al[mt][2] = tf32_of(h2 - __uint_as_float(Ah[mt][2]));
            Al[mt][3] = tf32_of(h3 - __uint_as_float(Ah[mt][3]));
        }
        #pragma unroll
        for (int nt = 0; nt < 4; ++nt) {
            const int bo = f1 * 36 + nt * 8 + lq;
            unsigned b0h = sW2h[bo], b1h = sW2h[bo + 4 * 36];
            unsigned b0l = sW2l[bo], b1l = sW2l[bo + 4 * 36];
            #pragma unroll
            for (int mt = 0; mt < 2; ++mt) {
                mma_tf32(D[mt][nt], Ah[mt], b0h, b1h);
                mma_tf32(D[mt][nt], Ah[mt], b0l, b1l);
                mma_tf32(D[mt][nt], Al[mt], b0h, b1h);
            }
        }
    }

    const size_t base = (((size_t)b * 32) + a0 + w) * 1024;
    #pragma unroll
    for (int mt = 0; mt < 2; ++mt) {
        #pragma unroll
        for (int nt = 0; nt < 4; ++nt) {
            const int i1 = mt * 16 + lq;
            const int n  = nt * 8 + 2 * lr;
            *reinterpret_cast<float2*>(&out[base + i1 * 32 + n]) =
                make_float2(D[mt][nt][0], D[mt][nt][1]);
            *reinterpret_cast<float2*>(&out[base + (i1 + 8) * 32 + n]) =
                make_float2(D[mt][nt][2], D[mt][nt][3]);
        }
    }
}

// ---------------------------------------------------------------------------
extern "C" void kernel_launch(void* const* d_in, const int* in_sizes, int n_in,
                              void* d_out, int out_size) {
    const float* states         = (const float*)d_in[0];
    const float* policies       = (const float*)d_in[1];
    const float* actions        = (const float*)d_in[2];
    const float* states_people  = (const float*)d_in[3];
    const float* actions_people = (const float*)d_in[4];
    const float* Wk  = (const float*)d_in[5];
    const float* Wq  = (const float*)d_in[6];
    const float* Wv  = (const float*)d_in[7];
    const float* Wkp = (const float*)d_in[8];
    const float* Wqp = (const float*)d_in[9];
    const float* Wvp = (const float*)d_in[10];
    const float* Wf1 = (const float*)d_in[11];
    const float* Wf2 = (const float*)d_in[12];
    float* out = (float*)d_out;

    k0_all<<<264, 256>>>(Wq, Wk, Wqp, Wkp, Wf2);

    cudaFuncSetAttribute(k1_batch, cudaFuncAttributeMaxDynamicSharedMemorySize, SM1_BYTES);
    k1_batch<<<256, 256, SM1_BYTES>>>(states, policies, actions,
                                      states_people, actions_people,
                                      Wv, Wvp, Wf1, out);

    k2_value<<<1024, 256>>>(out);
}

// round 10
// speedup vs baseline: 1.1053x; 1.0734x over previous
#include <cuda_runtime.h>
#include <math.h>

#define BB   256

// out layout: value [B,32,32,32] | weight [B,32,32] | wp [B,32,32]
#define WOFF      (8388608ull)
#define WPOFF     (8650752ull)

typedef unsigned long long ull;

__device__ float g_M [128 * 128];
__device__ float g_Mp[128 * 128];
__device__ unsigned g_W2h[64 * 32];
__device__ unsigned g_W2l[64 * 32];

// ---- packed f32x2 helpers ----
__device__ __forceinline__ ull pk2(float v) {
    ull r; asm("mov.b64 %0, {%1, %1};" : "=l"(r) : "f"(v)); return r;
}
__device__ __forceinline__ ull ffma2(ull a, ull b, ull c) {
    ull d; asm("fma.rn.f32x2 %0, %1, %2, %3;" : "=l"(d) : "l"(a), "l"(b), "l"(c)); return d;
}
__device__ __forceinline__ float2 upk2(ull v) {
    float2 f; asm("mov.b64 {%0, %1}, %2;" : "=f"(f.x), "=f"(f.y) : "l"(v)); return f;
}

// ---- tf32 helpers ----
__device__ __forceinline__ unsigned tf32_of(float x) {
    unsigned r; asm("cvt.rna.tf32.f32 %0, %1;" : "=r"(r) : "f"(x)); return r;
}
__device__ __forceinline__ void mma_tf32(float d[4], const unsigned a[4],
                                         unsigned b0, unsigned b1) {
    asm("mma.sync.aligned.m16n8k8.row.col.f32.tf32.tf32.f32 "
        "{%0,%1,%2,%3}, {%4,%5,%6,%7}, {%8,%9}, {%0,%1,%2,%3};"
        : "+f"(d[0]), "+f"(d[1]), "+f"(d[2]), "+f"(d[3])
        : "r"(a[0]), "r"(a[1]), "r"(a[2]), "r"(a[3]), "r"(b0), "r"(b1));
}

__device__ __forceinline__ float warp_max(float v) {
    #pragma unroll
    for (int o = 16; o; o >>= 1) v = fmaxf(v, __shfl_xor_sync(0xffffffffu, v, o));
    return v;
}
__device__ __forceinline__ float warp_sum(float v) {
    #pragma unroll
    for (int o = 16; o; o >>= 1) v += __shfl_xor_sync(0xffffffffu, v, o);
    return v;
}

// ---------------------------------------------------------------------------
// Kernel 0 (round-9 measured, 9.0us): M/Mp GEMMs + W2 hi/lo split.
// ---------------------------------------------------------------------------
__global__ void k0_all(const float* __restrict__ Wq, const float* __restrict__ Wk,
                       const float* __restrict__ Wqp, const float* __restrict__ Wkp,
                       const float* __restrict__ Wf2) {
    const int bx = blockIdx.x;
    const int t  = threadIdx.x;
    if (bx >= 256) {
        int idx = (bx - 256) * 256 + t;          // 0..2047
        float v = Wf2[idx];
        unsigned h = tf32_of(v);
        g_W2h[idx] = h;
        g_W2l[idx] = tf32_of(v - __uint_as_float(h));
        return;
    }
    __shared__ float sA[8 * 128];
    __shared__ float sB[16 * 129];
    __shared__ float sR[128 * 2];
    const int mat = bx >> 7;
    const int e0  = ((bx >> 3) & 15) * 8;
    const int c0  = (bx & 7) * 16;
    const float* A  = mat ? Wqp : Wq;
    const float* Bm = mat ? Wkp : Wk;
    float* out      = mat ? g_Mp : g_M;
    for (int i = t; i < 1024; i += 256) sA[i] = A[e0 * 128 + i];
    for (int i = t; i < 2048; i += 256) {
        int r = i >> 7, d = i & 127;
        sB[r * 129 + d] = Bm[(c0 + r) * 128 + d];
    }
    __syncthreads();
    const int kh = t >> 7, r = (t >> 4) & 7, c = t & 15;
    float acc = 0.f;
    const int d0 = kh * 64;
    #pragma unroll 8
    for (int d = 0; d < 64; ++d)
        acc = fmaf(sA[r * 128 + d0 + d], sB[c * 129 + d0 + d], acc);
    sR[(r * 16 + c) * 2 + kh] = acc;
    __syncthreads();
    if (t < 128) {
        int rr = t >> 4, cc = t & 15;
        out[(e0 + rr) * 128 + c0 + cc] = sR[t * 2] + sR[t * 2 + 1];
    }
}

// ---------------------------------------------------------------------------
// k1 staged fp32 GEMM cores (round-7 proven).
// ---------------------------------------------------------------------------
__device__ __forceinline__ void mm_chunk128(const float* __restrict__ X, int xstr, int e0,
                                            const float* __restrict__ Ws,
                                            ull acc[4][2], int r0, int l) {
    #pragma unroll 4
    for (int e = 0; e < 32; ++e) {
        ulonglong2 wv = *reinterpret_cast<const ulonglong2*>(&Ws[e * 128 + 4 * l]);
        #pragma unroll
        for (int r = 0; r < 4; ++r) {
            ull xx = pk2(X[(r0 + r) * xstr + e0 + e]);
            acc[r][0] = ffma2(xx, wv.x, acc[r][0]);
            acc[r][1] = ffma2(xx, wv.y, acc[r][1]);
        }
    }
}

__device__ __forceinline__ void mm_chunk64(const float* __restrict__ X, int e0,
                                           const float* __restrict__ Ws,
                                           ull acc[4], int r0, int l) {
    #pragma unroll 4
    for (int e = 0; e < 64; ++e) {
        ull wv = *reinterpret_cast<const ull*>(&Ws[e * 64 + 2 * l]);
        #pragma unroll
        for (int r = 0; r < 4; ++r)
            acc[r] = ffma2(pk2(X[(r0 + r) * 128 + e0 + e]), wv, acc[r]);
    }
}

__device__ __forceinline__ void store128(float* __restrict__ Y, ull acc[4][2],
                                         int r0, int l, bool do_tanh) {
    #pragma unroll
    for (int r = 0; r < 4; ++r) {
        float2 p0 = upk2(acc[r][0]);
        float2 p1 = upk2(acc[r][1]);
        float4 v = make_float4(p0.x, p0.y, p1.x, p1.y);
        if (do_tanh) { v.x = tanhf(v.x); v.y = tanhf(v.y); v.z = tanhf(v.z); v.w = tanhf(v.w); }
        *reinterpret_cast<float4*>(&Y[(r0 + r) * 128 + 4 * l]) = v;
    }
}

// ---------------------------------------------------------------------------
// Kernel 1 (fused): per-batch block; ends with the tc value GEMM.
// smem = 99,200 B -> 2 blocks/SM.
// ---------------------------------------------------------------------------
#define SM1_BYTES 99200
#define SOFTMAX_SCALE 0.08838834764831843f   // 1/sqrt(128)

#define STAGE(SRC) do {                                                    \
    __syncthreads();                                                       \
    { const float4* s4 = reinterpret_cast<const float4*>(SRC);            \
      float4* d4 = reinterpret_cast<float4*>(s_Wst);                      \
      for (int i = t; i < 1024; i += 256) d4[i] = s4[i]; }                \
    __syncthreads();                                                       \
} while (0)

extern "C" __global__ void __launch_bounds__(256, 2)
k1_fused(const float* __restrict__ states, const float* __restrict__ policies,
         const float* __restrict__ actions, const float* __restrict__ states_people,
         const float* __restrict__ actions_people,
         const float* __restrict__ Wv, const float* __restrict__ Wvp,
         const float* __restrict__ Wf1, float* __restrict__ out) {
    extern __shared__ __align__(16) float sm[];
    float* s_oa  = sm;                 // 32 x 129   (late: sU 32x64)
    float* s_oap = s_oa  + 4128;       // 32 x 129   (late: sW2h 64x36 unsigned)
    float* s_t   = s_oap + 4128;       // 32 x 128   (late: sW2l 64x36 unsigned)
    float* s_w   = s_t   + 4096;       // 32 x 32
    float* s_wp  = s_w   + 1024;       // 32 x 33
    float* s_A1  = s_wp  + 1056;       // 32 x 64  (early: sc 32x33)
    float* s_C1  = s_A1  + 2048;       // 32 x 64  (early: sp 32x33)
    float* s_Wst = s_C1  + 2048;       // 4096 floats staged weights
    float* s_V   = s_Wst + 4096;       // 32 x 68  V (stride 68: conflict-free frag reads)
    float* s_sc  = s_A1;
    float* s_sp  = s_C1;
    float*    sU   = s_oa;                                        // overlay
    unsigned* sW2h = reinterpret_cast<unsigned*>(s_oap);          // overlay
    unsigned* sW2l = reinterpret_cast<unsigned*>(s_t);            // overlay

    const int b = blockIdx.x;
    const int t = threadIdx.x;
    const int w = t >> 5, l = t & 31, r0 = 4 * w;

    const float* ac = actions  + (size_t)b * 1024;
    const float* po = policies + (size_t)b * 1024;

    float d_r[4];
    #pragma unroll
    for (int r = 0; r < 4; ++r)
        d_r[r] = po[(r0 + r) * 32 + l] - ac[(r0 + r) * 32 + l];

    // --- load inputs ---
    {
        const float* st  = states         + (size_t)b * 32 * 96;
        const float* stp = states_people  + (size_t)b * 32 * 96;
        const float* acp = actions_people + (size_t)b * 1024;
        for (int idx = t; idx < 4096; idx += 256) {
            int i = idx >> 7, c = idx & 127;
            s_oa [i * 129 + c] = (c < 96) ? st [i * 96 + c] : ac [i * 32 + c - 96];
            s_oap[i * 129 + c] = (c < 96) ? stp[i * 96 + c] : acp[i * 32 + c - 96];
        }
    }

    // --- t = oa @ M (staged); scores -> sc ---
    {
        ull a1[4][2] = {{0,0},{0,0},{0,0},{0,0}};
        #pragma unroll 1
        for (int ck = 0; ck < 4; ++ck) {
            STAGE(g_M + ck * 4096);
            mm_chunk128(s_oa, 129, ck * 32, s_Wst, a1, r0, l);
        }
        store128(s_t, a1, r0, l, false);
        float a0 = 0, s1 = 0, s2 = 0, s3 = 0;
        #pragma unroll 4
        for (int f = 0; f < 128; ++f) {
            float oj = s_oa[l * 129 + f];
            a0 = fmaf(s_t[(r0 + 0) * 128 + f], oj, a0);
            s1 = fmaf(s_t[(r0 + 1) * 128 + f], oj, s1);
            s2 = fmaf(s_t[(r0 + 2) * 128 + f], oj, s2);
            s3 = fmaf(s_t[(r0 + 3) * 128 + f], oj, s3);
        }
        s_sc[(r0 + 0) * 33 + l] = a0;  s_sc[(r0 + 1) * 33 + l] = s1;
        s_sc[(r0 + 2) * 33 + l] = s2;  s_sc[(r0 + 3) * 33 + l] = s3;
    }

    // --- tp = oa @ Mp (staged); scores_p -> sp ---
    {
        ull a2[4][2] = {{0,0},{0,0},{0,0},{0,0}};
        #pragma unroll 1
        for (int ck = 0; ck < 4; ++ck) {
            STAGE(g_Mp + ck * 4096);
            mm_chunk128(s_oa, 129, ck * 32, s_Wst, a2, r0, l);
        }
        store128(s_t, a2, r0, l, false);
        float c0 = 0, c1 = 0, c2 = 0, c3 = 0;
        #pragma unroll 4
        for (int f = 0; f < 128; ++f) {
            float pj = s_oap[l * 129 + f];
            c0 = fmaf(s_t[(r0 + 0) * 128 + f], pj, c0);
            c1 = fmaf(s_t[(r0 + 1) * 128 + f], pj, c1);
            c2 = fmaf(s_t[(r0 + 2) * 128 + f], pj, c2);
            c3 = fmaf(s_t[(r0 + 3) * 128 + f], pj, c3);
        }
        s_sp[(r0 + 0) * 33 + l] = c0;  s_sp[(r0 + 1) * 33 + l] = c1;
        s_sp[(r0 + 2) * 33 + l] = c2;  s_sp[(r0 + 3) * 33 + l] = c3;
    }
    __syncthreads();   // sc/sp complete

    // --- column softmaxes ---
    {
        #pragma unroll
        for (int k = 0; k < 4; ++k) {
            int a = w + 8 * k;
            float v  = s_sc[l * 33 + a] * SOFTMAX_SCALE;
            float m  = warp_max(v);
            float e  = expf(v - m);
            float s  = warp_sum(e);
            float wg = e / s;
            s_w[a * 32 + l] = wg;
            out[WOFF + ((size_t)b * 32 + a) * 32 + l] = wg;
            float v2 = s_sp[l * 33 + a] * SOFTMAX_SCALE;
            float m2 = warp_max(v2);
            float e2 = expf(v2 - m2);
            float s2 = warp_sum(e2);
            s_wp[l * 33 + a] = e2 / s2;
        }
    }
    __syncthreads();   // frees sc/sp regions for A1/C1

    // === va -> A1 ; vp -> V(smem) ; avp -> C1 ===
    ull a1regs[4];
    {
        ull av[4][2] = {{0,0},{0,0},{0,0},{0,0}};
        #pragma unroll 1
        for (int ck = 0; ck < 4; ++ck) {
            STAGE(Wv + ck * 4096);
            mm_chunk128(s_oa, 129, ck * 32, s_Wst, av, r0, l);
        }
        ull va_pre[4][2];
        #pragma unroll
        for (int r = 0; r < 4; ++r) { va_pre[r][0] = av[r][0]; va_pre[r][1] = av[r][1]; }
        store128(s_t, av, r0, l, true);          // va

        // A1 = va @ Wf1_top
        {
            ull acc[4] = {0, 0, 0, 0};
            #pragma unroll 1
            for (int ck = 0; ck < 2; ++ck) {
                STAGE(Wf1 + ck * 4096);
                mm_chunk64(s_t, ck * 64, s_Wst, acc, r0, l);
            }
            #pragma unroll
            for (int r = 0; r < 4; ++r) {
                a1regs[r] = acc[r];
                *reinterpret_cast<float2*>(&s_A1[(r0 + r) * 64 + 2 * l]) = upk2(acc[r]);
            }
        }

        // vp = tanh(va_pre + (pol-act) @ Wv[96:,:])
        {
            STAGE(Wv + 96 * 128);
            #pragma unroll 4
            for (int e = 0; e < 32; ++e) {
                ulonglong2 wv = *reinterpret_cast<const ulonglong2*>(&s_Wst[e * 128 + 4 * l]);
                #pragma unroll
                for (int r = 0; r < 4; ++r) {
                    ull xx = pk2(__shfl_sync(0xffffffffu, d_r[r], e));
                    va_pre[r][0] = ffma2(xx, wv.x, va_pre[r][0]);
                    va_pre[r][1] = ffma2(xx, wv.y, va_pre[r][1]);
                }
            }
            store128(s_t, va_pre, r0, l, true);  // vp
        }

        // V = (vp @ Wf1_top - A1) / 32 -> s_V (stride 68)
        {
            ull acc[4] = {0, 0, 0, 0};
            #pragma unroll 1
            for (int ck = 0; ck < 2; ++ck) {
                STAGE(Wf1 + ck * 4096);
                mm_chunk64(s_t, ck * 64, s_Wst, acc, r0, l);
            }
            #pragma unroll
            for (int r = 0; r < 4; ++r) {
                float2 p = upk2(acc[r]);
                float2 a = upk2(a1regs[r]);
                *reinterpret_cast<float2*>(&s_V[(r0 + r) * 68 + 2 * l]) =
                    make_float2((p.x - a.x) * 0.03125f, (p.y - a.y) * 0.03125f);
            }
        }

        // avp = tanh(oap @ Wvp) ; C1 = avp @ Wf1_bot
        {
            ull ap[4][2] = {{0,0},{0,0},{0,0},{0,0}};
            #pragma unroll 1
            for (int ck = 0; ck < 4; ++ck) {
                STAGE(Wvp + ck * 4096);
                mm_chunk128(s_oap, 129, ck * 32, s_Wst, ap, r0, l);
            }
            store128(s_t, ap, r0, l, true);
            ull acc[4] = {0, 0, 0, 0};
            #pragma unroll 1
            for (int ck = 0; ck < 2; ++ck) {
                STAGE(Wf1 + 8192 + ck * 4096);
                mm_chunk64(s_t, ck * 64, s_Wst, acc, r0, l);
            }
            #pragma unroll
            for (int r = 0; r < 4; ++r)
                *reinterpret_cast<float2*>(&s_C1[(r0 + r) * 64 + 2 * l]) = upk2(acc[r]);
        }
    }
    __syncthreads();   // A1/C1 complete; s_oa/s_oap/s_t now dead -> overlays

    // --- wp to global ---
    for (int idx = t; idx < 1024; idx += 256)
        out[WPOFF + (size_t)b * 1024 + idx] = s_wp[(idx >> 5) * 33 + (idx & 31)];

    // --- U[a] -> sU (s_oa overlay), warp rows r0..r0+3 ---
    {
        const ull* A1u = reinterpret_cast<const ull*>(s_A1);
        const ull* C1u = reinterpret_cast<const ull*>(s_C1);
        ull uacc[4] = {0, 0, 0, 0};
        #pragma unroll 4
        for (int j = 0; j < 32; ++j) {
            ull wv = A1u[j * 32 + l];
            #pragma unroll
            for (int r = 0; r < 4; ++r)
                uacc[r] = ffma2(pk2(s_w[(r0 + r) * 32 + j]), wv, uacc[r]);
        }
        #pragma unroll 4
        for (int p = 0; p < 32; ++p) {
            ull wv = C1u[p * 32 + l];
            #pragma unroll
            for (int r = 0; r < 4; ++r)
                uacc[r] = ffma2(pk2(s_wp[(r0 + r) * 33 + p]), wv, uacc[r]);
        }
        #pragma unroll
        for (int r = 0; r < 4; ++r) {
            float2 p = upk2(uacc[r]);
            *reinterpret_cast<float2*>(&sU[(r0 + r) * 64 + 2 * l]) =
                make_float2(p.x * 0.03125f, p.y * 0.03125f);
        }
    }

    // --- stage W2 hi/lo into overlays (stride 36) ---
    for (int idx = t; idx < 2048; idx += 256) {
        int f = idx >> 5, n = idx & 31;
        sW2h[f * 36 + n] = g_W2h[idx];
        sW2l[f * 36 + n] = g_W2l[idx];
    }
    __syncthreads();   // sU / sV / s_w / W2 overlays ready

    // === fused tc value epilogue: warp w handles a = 4w + r, r = 0..3 ===
    {
        const int lq = l >> 2, lr = l & 3;
        #pragma unroll 1
        for (int r = 0; r < 4; ++r) {
            const int a = r0 + r;
            const float* Urow = &sU[a * 64];
            const float* wrow = &s_w[a * 32];

            float Uf[8][2];
            #pragma unroll
            for (int kt = 0; kt < 8; ++kt) {
                Uf[kt][0] = Urow[kt * 8 + lr];
                Uf[kt][1] = Urow[kt * 8 + lr + 4];
            }
            float wm[2][2];
            #pragma unroll
            for (int mt = 0; mt < 2; ++mt) {
                wm[mt][0] = wrow[mt * 16 + lq];
                wm[mt][1] = wrow[mt * 16 + lq + 8];
            }

            float D[2][4][4];
            #pragma unroll
            for (int mt = 0; mt < 2; ++mt)
                #pragma unroll
                for (int nt = 0; nt < 4; ++nt)
                    #pragma unroll
                    for (int q = 0; q < 4; ++q) D[mt][nt][q] = 0.f;

            #pragma unroll
            for (int kt = 0; kt < 8; ++kt) {
                const int f1 = kt * 8 + lr;
                unsigned Ah[2][4], Al[2][4];
                #pragma unroll
                for (int mt = 0; mt < 2; ++mt) {
                    const int i1 = mt * 16 + lq;
                    float v00 = s_V[i1 * 68 + f1];
                    float v10 = s_V[(i1 + 8) * 68 + f1];
                    float v01 = s_V[i1 * 68 + f1 + 4];
                    float v11 = s_V[(i1 + 8) * 68 + f1 + 4];
                    float h0 = fmaf(wm[mt][0], v00, Uf[kt][0]);
                    float h1 = fmaf(wm[mt][1], v10, Uf[kt][0]);
                    float h2 = fmaf(wm[mt][0], v01, Uf[kt][1]);
                    float h3 = fmaf(wm[mt][1], v11, Uf[kt][1]);
                    h0 = fmaxf(h0, 0.f) + 0.01f * fminf(h0, 0.f);
                    h1 = fmaxf(h1, 0.f) + 0.01f * fminf(h1, 0.f);
                    h2 = fmaxf(h2, 0.f) + 0.01f * fminf(h2, 0.f);
                    h3 = fmaxf(h3, 0.f) + 0.01f * fminf(h3, 0.f);
                    Ah[mt][0] = tf32_of(h0);
                    Ah[mt][1] = tf32_of(h1);
                    Ah[mt][2] = tf32_of(h2);
                    Ah[mt][3] = tf32_of(h3);
                    Al[mt][0] = tf32_of(h0 - __uint_as_float(Ah[mt][0]));
                    Al[mt][1] = tf32_of(h1 - __uint_as_float(Ah[mt][1]));
                    Al[mt][2] = tf32_of(h2 - __uint_as_float(Ah[mt][2]));
                    Al[mt][3] = tf32_of(h3 - __uint_as_float(Ah[mt][3]));
                }
                #pragma unroll
                for (int nt = 0; nt < 4; ++nt) {
                    const int bo = f1 * 36 + nt * 8 + lq;
                    unsigned b0h = sW2h[bo], b1h = sW2h[bo + 4 * 36];
                    unsigned b0l = sW2l[bo], b1l = sW2l[bo + 4 * 36];
                    #pragma unroll
                    for (int mt = 0; mt < 2; ++mt) {
                        mma_tf32(D[mt][nt], Ah[mt], b0h, b1h);
                        mma_tf32(D[mt][nt], Ah[mt], b0l, b1l);
                        mma_tf32(D[mt][nt], Al[mt], b0h, b1h);
                    }
                }
            }

            const size_t base = (((size_t)b * 32) + a) * 1024;
            #pragma unroll
            for (int mt = 0; mt < 2; ++mt) {
                #pragma unroll
                for (int nt = 0; nt < 4; ++nt) {
                    const int i1 = mt * 16 + lq;
                    const int n  = nt * 8 + 2 * lr;
                    *reinterpret_cast<float2*>(&out[base + i1 * 32 + n]) =
                        make_float2(D[mt][nt][0], D[mt][nt][1]);
                    *reinterpret_cast<float2*>(&out[base + (i1 + 8) * 32 + n]) =
                        make_float2(D[mt][nt][2], D[mt][nt][3]);
                }
            }
        }
    }
}

// ---------------------------------------------------------------------------
extern "C" void kernel_launch(void* const* d_in, const int* in_sizes, int n_in,
                              void* d_out, int out_size) {
    const float* states         = (const float*)d_in[0];
    const float* policies       = (const float*)d_in[1];
    const float* actions        = (const float*)d_in[2];
    const float* states_people  = (const float*)d_in[3];
    const float* actions_people = (const float*)d_in[4];
    const float* Wk  = (const float*)d_in[5];
    const float* Wq  = (const float*)d_in[6];
    const float* Wv  = (const float*)d_in[7];
    const float* Wkp = (const float*)d_in[8];
    const float* Wqp = (const float*)d_in[9];
    const float* Wvp = (const float*)d_in[10];
    const float* Wf1 = (const float*)d_in[11];
    const float* Wf2 = (const float*)d_in[12];
    float* out = (float*)d_out;

    k0_all<<<264, 256>>>(Wq, Wk, Wqp, Wkp, Wf2);

    cudaFuncSetAttribute(k1_fused, cudaFuncAttributeMaxDynamicSharedMemorySize, SM1_BYTES);
    k1_fused<<<256, 256, SM1_BYTES>>>(states, policies, actions,
                                      states_people, actions_people,
                                      Wv, Wvp, Wf1, out);
}